// round 10
// baseline (speedup 1.0000x reference)
#include <cuda_runtime.h>
#include <cuda_fp16.h>
#include <math.h>
#include <stdint.h>

#define B_TOK 16384
#define D_DIM 1024
#define H_DIM 256
#define E_NUM 8
#define TM    64
#define NTHR  256

// smem: H (gelu h, 64x512B swizzled) @0..32768 ; ring 2 x (A 8KB + B 32KB) @32768
#define H_OFF   0
#define RING    32768
#define ST_SZ   40960
#define ST_B    8192
#define DYN_SMEM 114688

// ---------------- device scratch ----------------
__device__ int    g_cnt[E_NUM];
__device__ int    g_tok[E_NUM][B_TOK];          // tok*2 + rank
__device__ float  g_wgt[E_NUM][B_TOK];
__device__ __half g_xh[(size_t)B_TOK * D_DIM];                 // x fp16
// tiled + pre-swizzled fp16 weights: [e][slice(k64)][n][64 halves swizzled]
__device__ __half g_w1h[(size_t)E_NUM * H_DIM * D_DIM];
__device__ __half g_w2h[(size_t)E_NUM * D_DIM * H_DIM];

// ---------------- helpers ----------------
__device__ __forceinline__ uint32_t smem_u32(const void* p) {
    uint32_t r;
    asm("{.reg .u64 t; cvta.to.shared.u64 t,%1; cvt.u32.u64 %0,t;}" : "=r"(r) : "l"(p));
    return r;
}
__device__ __forceinline__ void cp16(uint32_t s, const void* g) {
    asm volatile("cp.async.cg.shared.global [%0],[%1],16;" :: "r"(s), "l"(g));
}
__device__ __forceinline__ void cp_commit() {
    asm volatile("cp.async.commit_group;" ::: "memory");
}
template <int N> __device__ __forceinline__ void cp_wait() {
    asm volatile("cp.async.wait_group %0;" :: "n"(N) : "memory");
}
__device__ __forceinline__ void mbar_init(uint32_t mb, uint32_t cnt) {
    asm volatile("mbarrier.init.shared.b64 [%0], %1;" :: "r"(mb), "r"(cnt) : "memory");
}
__device__ __forceinline__ void mbar_expect(uint32_t mb, uint32_t bytes) {
    asm volatile("mbarrier.arrive.expect_tx.shared.b64 _, [%0], %1;"
                 :: "r"(mb), "r"(bytes) : "memory");
}
__device__ __forceinline__ void bulk_g2s(uint32_t dst, const void* src,
                                         uint32_t bytes, uint32_t mb) {
    asm volatile(
        "cp.async.bulk.shared::cluster.global.mbarrier::complete_tx::bytes "
        "[%0], [%1], %2, [%3];"
        :: "r"(dst), "l"(src), "r"(bytes), "r"(mb) : "memory");
}
__device__ __forceinline__ void mbar_wait(uint32_t mb, uint32_t ph) {
    asm volatile(
        "{.reg .pred P;\n\t"
        "WL%=:\n\t"
        "mbarrier.try_wait.parity.acquire.cta.shared::cta.b64 P,[%0],%1,0x989680;\n\t"
        "@P bra WD%=;\n\t"
        "bra WL%=;\n\t"
        "WD%=:}" :: "r"(mb), "r"(ph) : "memory");
}
__device__ __forceinline__ void ldsm4(uint32_t* r, uint32_t a) {
    asm volatile("ldmatrix.sync.aligned.m8n8.x4.shared.b16 {%0,%1,%2,%3},[%4];"
                 : "=r"(r[0]), "=r"(r[1]), "=r"(r[2]), "=r"(r[3]) : "r"(a));
}
__device__ __forceinline__ void mma16(float* c, const uint32_t* a, const uint32_t* b) {
    asm volatile(
        "mma.sync.aligned.m16n8k16.row.col.f32.f16.f16.f32 "
        "{%0,%1,%2,%3},{%4,%5,%6,%7},{%8,%9},{%0,%1,%2,%3};"
        : "+f"(c[0]), "+f"(c[1]), "+f"(c[2]), "+f"(c[3])
        : "r"(a[0]), "r"(a[1]), "r"(a[2]), "r"(a[3]), "r"(b[0]), "r"(b[1]));
}

// ---------------- weight prep: [E][K][N] fp32 -> [e][k/64][n][64] fp16 swizzled ----------------
__global__ void prep_w_kernel(const float* __restrict__ src, __half* __restrict__ dst,
                              int K, int N, int do_zero) {
    __shared__ float tile[64][33];
    if (do_zero && blockIdx.x == 0 && blockIdx.y == 0 && blockIdx.z == 0 &&
        threadIdx.y == 0 && threadIdx.x < E_NUM)
        g_cnt[threadIdx.x] = 0;
    const int e = blockIdx.z, s = blockIdx.y, n0 = blockIdx.x * 32;
    const int tx = threadIdx.x, ty = threadIdx.y;      // 32 x 8
    const float* sp = src + (size_t)e * K * N + (size_t)s * 64 * N + n0;
#pragma unroll
    for (int dy = 0; dy < 8; dy++)
        tile[ty + dy * 8][tx] = sp[(size_t)(ty + dy * 8) * N + tx];
    __syncthreads();
    __half* dp = dst + (((size_t)e * (K / 64) + s) * N + n0) * 64;
    const int nn = n0 + tx;
#pragma unroll
    for (int dy = 0; dy < 4; dy++) {
        int k = (ty + dy * 8) * 2;
        __half2 v = __floats2half2_rn(tile[k][tx], tile[k + 1][tx]);
        *(__half2*)(dp + (size_t)tx * 64 + (((k >> 3) ^ (nn & 7)) << 3) + (k & 7)) = v;
    }
}

// ---------------- gate: logits + top-2 + scatter + x->fp16 + zero out ----------------
__global__ __launch_bounds__(512) void gate_kernel(
    const float* __restrict__ x, const float* __restrict__ gw,
    const float* __restrict__ gb, float* __restrict__ out)
{
    __shared__ float gws[E_NUM * D_DIM];
    const int tid = threadIdx.x;
    for (int i = tid; i < E_NUM * D_DIM; i += 512) {
        int e = i >> 10, d = i & 1023;
        gws[i] = gw[d * E_NUM + e];
    }
    {   // zero this block's 64 output rows
        float4 z = make_float4(0.f, 0.f, 0.f, 0.f);
        float4* o4 = (float4*)(out + (size_t)blockIdx.x * 64 * D_DIM);
        for (int i = tid; i < 64 * D_DIM / 4; i += 512) o4[i] = z;
    }
    __syncthreads();

    const int warp = tid >> 5, lane = tid & 31;
    const int tok0 = blockIdx.x * 64 + warp * 4;
    const int d0 = lane * 4;

    const float* xr = x    + (size_t)tok0 * D_DIM;
    __half*      xh = g_xh + (size_t)tok0 * D_DIM;

    float acc[4][E_NUM];
#pragma unroll
    for (int t = 0; t < 4; t++)
#pragma unroll
        for (int e = 0; e < E_NUM; e++) acc[t][e] = 0.f;

    float4 cur[4], nxt[4];
#pragma unroll
    for (int t = 0; t < 4; t++) cur[t] = *(const float4*)(xr + (size_t)t * D_DIM + d0);

#pragma unroll
    for (int j = 0; j < 8; j++) {
        const int dj = j * 128 + d0;
        if (j < 7) {
#pragma unroll
            for (int t = 0; t < 4; t++)
                nxt[t] = *(const float4*)(xr + (size_t)t * D_DIM + dj + 128);
        }
#pragma unroll
        for (int e = 0; e < E_NUM; e++) {
            float4 wv = *(const float4*)&gws[e * D_DIM + dj];
#pragma unroll
            for (int t = 0; t < 4; t++)
                acc[t][e] += cur[t].x * wv.x + cur[t].y * wv.y
                           + cur[t].z * wv.z + cur[t].w * wv.w;
        }
#pragma unroll
        for (int t = 0; t < 4; t++) {
            __half2 h0 = __floats2half2_rn(cur[t].x, cur[t].y);
            __half2 h1 = __floats2half2_rn(cur[t].z, cur[t].w);
            uint2 u = make_uint2(*(uint32_t*)&h0, *(uint32_t*)&h1);
            *(uint2*)(xh + (size_t)t * D_DIM + dj) = u;
        }
#pragma unroll
        for (int t = 0; t < 4; t++) cur[t] = nxt[t];
    }

#pragma unroll
    for (int t = 0; t < 4; t++)
#pragma unroll
        for (int e = 0; e < E_NUM; e++)
#pragma unroll
            for (int s = 16; s; s >>= 1)
                acc[t][e] += __shfl_xor_sync(0xffffffffu, acc[t][e], s);

    if (lane == 0) {
#pragma unroll
        for (int t = 0; t < 4; t++) {
            float l[E_NUM];
#pragma unroll
            for (int e = 0; e < E_NUM; e++) l[e] = acc[t][e] + gb[e];
            int i0 = 0;
#pragma unroll
            for (int e = 1; e < E_NUM; e++) if (l[e] > l[i0]) i0 = e;
            int i1 = (i0 == 0) ? 1 : 0;
#pragma unroll
            for (int e = 0; e < E_NUM; e++) if (e != i0 && l[e] > l[i1]) i1 = e;
            float e1 = expf(l[i1] - l[i0]);
            float s  = 1.0f + e1;
            int tok  = tok0 + t;
            int p0 = atomicAdd(&g_cnt[i0], 1);
            g_tok[i0][p0] = tok * 2 + 0; g_wgt[i0][p0] = 1.0f / s;
            int p1 = atomicAdd(&g_cnt[i1], 1);
            g_tok[i1][p1] = tok * 2 + 1; g_wgt[i1][p1] = e1 / s;
        }
    }
}

// ---------------- fused expert: GEMM1 -> gelu (smem) -> GEMM2 -> red.add ----------------
__global__ void __launch_bounds__(NTHR, 2) expert_kernel(
    const float* __restrict__ b1, const float* __restrict__ b2,
    float* __restrict__ out)
{
    const int e     = blockIdx.y;
    const int cnt   = g_cnt[e];
    const int start = blockIdx.x * TM;
    if (start >= cnt) return;
    const int mcount = min(TM, cnt - start);

    __shared__ int   tids_s[TM];
    __shared__ float wts_s[TM];
    __shared__ __align__(8) uint64_t mbar_s[2];
    extern __shared__ __align__(16) char smem[];
    const uint32_t sb = smem_u32(smem);

    const int tid = threadIdx.x;
    if (tid < TM) {
        bool v = tid < mcount;
        int  src = v ? (start + tid) : start;
        tids_s[tid] = g_tok[e][src] >> 1;
        wts_s[tid]  = v ? g_wgt[e][src] : 0.f;
    }
    const uint32_t mb[2] = { smem_u32(&mbar_s[0]), smem_u32(&mbar_s[1]) };
    if (tid == 0) { mbar_init(mb[0], 1); mbar_init(mb[1], 1); }
    __syncthreads();

    const int warp = tid >> 5, lane = tid & 31;
    const int wm = warp & 1, wn = warp >> 1;            // 2(M,32) x 4(N,64)
    const int sub = lane >> 3, rin = lane & 7;
    const int g = lane >> 2, tg = lane & 3;
    const int arl = (sub & 1) * 8 + rin, auo = sub >> 1;
    const int brl = ((sub >> 1) & 1) * 8 + rin, buo = sub & 1;

    const __half* w1h = g_w1h + (size_t)e * 16 * 16384;  // [16 slices][32KB]
    const __half* w2h = g_w2h + (size_t)e * 4 * 65536;   // [4 slices][1024 n][64]
    const float*  b1e = b1 + e * H_DIM;
    const float*  b2e = b2 + e * D_DIM;

    const int r0 = tid >> 2, u0 = tid & 3, u1 = u0 + 4;
    const __half* ga0 = g_xh + (size_t)tids_s[r0] * D_DIM + u0 * 8;
    const __half* ga1 = g_xh + (size_t)tids_s[r0] * D_DIM + u1 * 8;
    const uint32_t sa0 = r0 * 128 + ((u0 ^ (r0 & 7)) << 4);
    const uint32_t sa1 = r0 * 128 + ((u1 ^ (r0 & 7)) << 4);

    float c[2][8][4];
#pragma unroll
    for (int mi = 0; mi < 2; mi++)
#pragma unroll
        for (int ni = 0; ni < 8; ni++)
#pragma unroll
            for (int q = 0; q < 4; q++) c[mi][ni][q] = 0.f;

    int ph[2] = {0, 0};

    // =============== GEMM1: x[64,1024] @ w1^T -> c ===============
    if (tid == 0) { mbar_expect(mb[0], 32768); bulk_g2s(sb + RING + ST_B, w1h, 32768, mb[0]); }
    cp16(sb + RING + sa0, ga0); cp16(sb + RING + sa1, ga1); cp_commit();

    for (int i = 0; i < 16; i++) {
        const int b = i & 1;
        cp_wait<0>();
        mbar_wait(mb[b], ph[b]); ph[b] ^= 1;
        __syncthreads();
        if (i + 1 < 16) {
            const int nb = b ^ 1;
            const uint32_t st = sb + RING + nb * ST_SZ;
            if (tid == 0) {
                mbar_expect(mb[nb], 32768);
                bulk_g2s(st + ST_B, w1h + (size_t)(i + 1) * 16384, 32768, mb[nb]);
            }
            cp16(st + sa0, ga0 + (i + 1) * 64);
            cp16(st + sa1, ga1 + (i + 1) * 64);
            cp_commit();
        }
        const uint32_t Ab = sb + RING + b * ST_SZ;
        const uint32_t Bb = Ab + ST_B;
#pragma unroll
        for (int kk = 0; kk < 4; kk++) {
            uint32_t a[2][4], bf[4][4];
#pragma unroll
            for (int mi = 0; mi < 2; mi++) {
                int row = wm * 32 + mi * 16 + arl;
                int u   = 2 * kk + auo;
                ldsm4(a[mi], Ab + row * 128 + ((u ^ (row & 7)) << 4));
            }
#pragma unroll
            for (int p = 0; p < 4; p++) {
                int row = wn * 64 + p * 16 + brl;
                int u   = 2 * kk + buo;
                ldsm4(bf[p], Bb + row * 128 + ((u ^ (row & 7)) << 4));
            }
#pragma unroll
            for (int mi = 0; mi < 2; mi++)
#pragma unroll
                for (int ni = 0; ni < 8; ni++)
                    mma16(c[mi][ni], a[mi], &bf[ni >> 1][(ni & 1) * 2]);
        }
    }

    // prefetch GEMM2 tile 0 into buf0 (consumed at GEMM1 slice 14; safe)
    if (tid == 0) { mbar_expect(mb[0], 32768); bulk_g2s(sb + RING + ST_B, w2h, 32768, mb[0]); }
    __syncthreads();   // all warps done reading buf1 (slice 15)

    // =============== gelu epilogue -> H (64 rows x 512B, swizzled for ldsm) ===============
#pragma unroll
    for (int mi = 0; mi < 2; mi++) {
#pragma unroll
        for (int ni = 0; ni < 8; ni++) {
            int col = wn * 64 + ni * 8 + tg * 2;          // halves, even
            float bb0 = b1e[col], bb1 = b1e[col + 1];
            int u = col >> 3, bo = (col * 2) & 15;
#pragma unroll
            for (int h = 0; h < 2; h++) {
                int row = wm * 32 + mi * 16 + g + h * 8;
                float v0 = c[mi][ni][h * 2]     + bb0;
                float v1 = c[mi][ni][h * 2 + 1] + bb1;
                v0 = 0.5f * v0 * (1.0f + erff(v0 * 0.70710678f));
                v1 = 0.5f * v1 * (1.0f + erff(v1 * 0.70710678f));
                __half2 hv = __floats2half2_rn(v0, v1);
                asm volatile("st.shared.b32 [%0],%1;"
                             :: "r"(sb + H_OFF + row * 512 + ((u ^ (row & 7)) << 4) + bo),
                                "r"(*(uint32_t*)&hv));
            }
        }
    }
    __syncthreads();   // H visible to all warps

    // =============== GEMM2: 4 N-panels x 4 k64-slices ===============
    for (int sc = 0; sc < 16; sc++) {
        const int py = sc >> 2, i = sc & 3, b = sc & 1;
        mbar_wait(mb[b], ph[b]); ph[b] ^= 1;
        __syncthreads();
        if (sc + 1 < 16) {
            const int nsc = sc + 1, nb = b ^ 1;
            if (tid == 0) {
                mbar_expect(mb[nb], 32768);
                bulk_g2s(sb + RING + nb * ST_SZ + ST_B,
                         w2h + (((size_t)(nsc & 3) * 1024) + (size_t)(nsc >> 2) * 256) * 64,
                         32768, mb[nb]);
            }
        }
        if (i == 0) {
#pragma unroll
            for (int mi = 0; mi < 2; mi++)
#pragma unroll
                for (int ni = 0; ni < 8; ni++)
#pragma unroll
                    for (int q = 0; q < 4; q++) c[mi][ni][q] = 0.f;
        }
        const uint32_t Bb = sb + RING + b * ST_SZ + ST_B;
#pragma unroll
        for (int kk = 0; kk < 4; kk++) {
            uint32_t a[2][4], bf[4][4];
#pragma unroll
            for (int mi = 0; mi < 2; mi++) {
                int row = wm * 32 + mi * 16 + arl;
                int u   = i * 8 + 2 * kk + auo;
                ldsm4(a[mi], sb + H_OFF + row * 512 + ((u ^ (row & 7)) << 4));
            }
#pragma unroll
            for (int p = 0; p < 4; p++) {
                int row = wn * 64 + p * 16 + brl;
                int u   = 2 * kk + buo;
                ldsm4(bf[p], Bb + row * 128 + ((u ^ (row & 7)) << 4));
            }
#pragma unroll
            for (int mi = 0; mi < 2; mi++)
#pragma unroll
                for (int ni = 0; ni < 8; ni++)
                    mma16(c[mi][ni], a[mi], &bf[ni >> 1][(ni & 1) * 2]);
        }

        if (i == 3) {   // panel complete: weighted red.add into out
#pragma unroll
            for (int mi = 0; mi < 2; mi++) {
#pragma unroll
                for (int h = 0; h < 2; h++) {
                    int r = wm * 32 + mi * 16 + g + h * 8;
                    if (r < mcount) {
                        float wt = wts_s[r];
                        float* dst = out + (size_t)tids_s[r] * D_DIM + py * 256;
#pragma unroll
                        for (int ni = 0; ni < 8; ni++) {
                            int col = wn * 64 + ni * 8 + tg * 2;
                            atomicAdd(dst + col,     wt * (c[mi][ni][h * 2]     + b2e[py * 256 + col]));
                            atomicAdd(dst + col + 1, wt * (c[mi][ni][h * 2 + 1] + b2e[py * 256 + col + 1]));
                        }
                    }
                }
            }
        }
    }
}

// ---------------- launch ----------------
extern "C" void kernel_launch(void* const* d_in, const int* in_sizes, int n_in,
                              void* d_out, int out_size) {
    const float* x  = (const float*)d_in[0];
    const float* gw = (const float*)d_in[1];
    const float* gb = (const float*)d_in[2];
    const float* w1 = (const float*)d_in[3];
    const float* b1 = (const float*)d_in[4];
    const float* w2 = (const float*)d_in[5];
    const float* b2 = (const float*)d_in[6];
    float* out = (float*)d_out;

    static __half* w1h_ptr = nullptr;
    static __half* w2h_ptr = nullptr;
    if (!w1h_ptr) {
        cudaGetSymbolAddress((void**)&w1h_ptr, g_w1h);
        cudaGetSymbolAddress((void**)&w2h_ptr, g_w2h);
        cudaFuncSetAttribute(expert_kernel,
                             cudaFuncAttributeMaxDynamicSharedMemorySize, DYN_SMEM);
    }

    prep_w_kernel<<<dim3(H_DIM / 32, D_DIM / 64, E_NUM), dim3(32, 8)>>>(
        w1, w1h_ptr, D_DIM, H_DIM, 1);
    prep_w_kernel<<<dim3(D_DIM / 32, H_DIM / 64, E_NUM), dim3(32, 8)>>>(
        w2, w2h_ptr, H_DIM, D_DIM, 0);
    gate_kernel<<<B_TOK / 64, 512>>>(x, gw, gb, out);
    expert_kernel<<<dim3(B_TOK / TM, E_NUM), NTHR, DYN_SMEM>>>(b1, b2, out);
}